// round 15
// baseline (speedup 1.0000x reference)
#include <cuda_runtime.h>
#include <cuda_fp16.h>
#include <cstdint>

// ---------------- problem constants ----------------
#define BB    4
#define NQ    384
#define NK    384
#define DE    64
#define DMSG  64
#define DFF   256
#define DOUT  64
#define DINV  256

#define TQ    16
#define TK    8
#define TM    128

#define LDA   136          // half pitch for W1 chunk tiles (k=128 + 8 pad)
#define LDKE  212          // float pitch for k-equi staging
#define LDAQH 264          // half pitch for sAqh/sAkh

#define PRE_ROWS 16
#define NPRE2 (BB * (NQ + NK) / PRE_ROWS)   // 192 blocks
#define NPREP 96

// ---------------- device scratch ----------------
__device__ __half g_Aqh[BB * NQ * DFF];
__device__ __half g_Akh[BB * NK * DFF];
__device__ __align__(16) __half g_W1T[DFF * LDA];        // [n=256][pitch 136]
// W2 fragment-major image: [c:4][kk:4][jp:4][lane:32] uint4 (verified layout, R9)
__device__ __align__(16) uint32_t g_W2F[4 * 4 * 4 * 32 * 4];   // 32768 B

// ---------------- SMEM map (bytes) — pair kernel ----------------
#define OFF_QE    0        // 16*192*4 = 12288
#define OFF_KE    12288    //  8*212*4 =  6784
#define OFF_AQH   19072    // 16*264*2 =  8448
#define OFF_AKH   27520    //  8*264*2 =  4224
#define OFF_W1C0  31744    // 17408
#define OFF_W1C1  49152    // 17408
#define OFF_B2    66560    //   256
#define SMEM_BYTES 66816

__device__ __forceinline__ uint32_t smem_u32(const void* p) {
    uint32_t a;
    asm("{ .reg .u64 t; cvta.to.shared.u64 t, %1; cvt.u32.u64 %0, t; }" : "=r"(a) : "l"(p));
    return a;
}
#define CP_ASYNC16(dst, src) \
    asm volatile("cp.async.cg.shared.global [%0], [%1], 16;" :: "r"(dst), "l"(src))
#define CP_COMMIT() asm volatile("cp.async.commit_group;" ::: "memory")
#define CP_WAIT(n)  asm volatile("cp.async.wait_group %0;" :: "n"(n) : "memory")

__device__ __forceinline__ void ldsm4(uint32_t& r0, uint32_t& r1, uint32_t& r2, uint32_t& r3,
                                      uint32_t addr) {
    asm volatile("ldmatrix.sync.aligned.m8n8.x4.shared.b16 {%0,%1,%2,%3}, [%4];"
        : "=r"(r0), "=r"(r1), "=r"(r2), "=r"(r3) : "r"(addr));
}
__device__ __forceinline__ void mma16816(float* c, uint32_t a0, uint32_t a1, uint32_t a2,
                                         uint32_t a3, uint32_t b0, uint32_t b1) {
    asm volatile(
        "mma.sync.aligned.m16n8k16.row.col.f32.f16.f16.f32 "
        "{%0,%1,%2,%3}, {%4,%5,%6,%7}, {%8,%9}, {%0,%1,%2,%3};"
        : "+f"(c[0]), "+f"(c[1]), "+f"(c[2]), "+f"(c[3])
        : "r"(a0), "r"(a1), "r"(a2), "r"(a3), "r"(b0), "r"(b1));
}
__device__ __forceinline__ uint32_t silu_h2(uint32_t xu) {
    uint32_t hxu, tu, res;
    asm("mul.rn.f16x2 %0, %1, %2;" : "=r"(hxu) : "r"(xu), "r"(0x38003800u));
    asm("tanh.approx.f16x2 %0, %1;" : "=r"(tu) : "r"(hxu));
    asm("fma.rn.f16x2 %0, %1, %2, %3;" : "=r"(res) : "r"(hxu), "r"(tu), "r"(hxu));
    return res;
}

// ---------------- packed f32x2 helpers ----------------
__device__ __forceinline__ uint64_t pk2(float2 v) {
    uint64_t r; asm("mov.b64 %0, {%1, %2};" : "=l"(r) : "f"(v.x), "f"(v.y)); return r;
}
__device__ __forceinline__ float2 upk2(uint64_t v) {
    float2 r; asm("mov.b64 {%0, %1}, %2;" : "=f"(r.x), "=f"(r.y) : "l"(v)); return r;
}
__device__ __forceinline__ uint64_t mul2_(uint64_t a, uint64_t b) {
    uint64_t d; asm("mul.rn.f32x2 %0, %1, %2;" : "=l"(d) : "l"(a), "l"(b)); return d;
}
__device__ __forceinline__ uint64_t add2_(uint64_t a, uint64_t b) {
    uint64_t d; asm("add.rn.f32x2 %0, %1, %2;" : "=l"(d) : "l"(a), "l"(b)); return d;
}
__device__ __forceinline__ uint64_t fma2_(uint64_t a, uint64_t b, uint64_t c) {
    uint64_t d; asm("fma.rn.f32x2 %0, %1, %2, %3;" : "=l"(d) : "l"(a), "l"(b), "l"(c)); return d;
}
__device__ __forceinline__ float sqrt_ap(float x) {
    float r; asm("sqrt.approx.f32 %0, %1;" : "=f"(r) : "f"(x)); return r;
}
#define NEGMASK2 0x8000000080000000ULL

// ---------------- prelude v2 (16 rows/block) + appended weight-prep ----------------
__global__ void __launch_bounds__(256) prelude_kernel(
    const float* __restrict__ q_inv, const float* __restrict__ k_inv,
    const float* __restrict__ Wq, const float* __restrict__ bq,
    const float* __restrict__ Wk, const float* __restrict__ bk,
    const float* __restrict__ W1, const float* __restrict__ b1,
    const float* __restrict__ W2)
{
    int blk = blockIdx.x;

    if (blk >= NPRE2) {
        // W1T (32768 halfs) + W2F (8192 uint32 fragments)
        int idx = (blk - NPRE2) * 256 + threadIdx.x;
        int total = DFF * 128 + 8192;
        for (; idx < total; idx += NPREP * 256) {
            if (idx < DFF * 128) {
                int n = idx >> 7, k = idx & 127;
                g_W1T[n * LDA + k] = __float2half(W1[(128 + k) * DFF + n]);
            } else {
                // B-frag image for mma m16n8k16 .col (layout verified in R9):
                // u32 i of lane L in tile (n0=jp*16, k0=c*64+kk*16):
                //   n = n0 + ((i>>1)&1)*8 + (L>>2);  k = k0 + (i&1)*8 + (L&3)*2
                int j    = idx - DFF * 128;
                int i    = j & 3;
                int lane = (j >> 2) & 31;
                int jp   = (j >> 7) & 3;
                int kk   = (j >> 9) & 3;
                int c    = j >> 11;
                int n = jp * 16 + ((i >> 1) & 1) * 8 + (lane >> 2);
                int k = c * 64 + kk * 16 + (i & 1) * 8 + (lane & 3) * 2;
                __half2 v = __floats2half2_rn(W2[k * DOUT + n], W2[(k + 1) * DOUT + n]);
                g_W2F[j] = *(uint32_t*)&v;
            }
        }
        return;
    }

    bool isQ = blk < (BB * NQ / PRE_ROWS);
    int rowbase = (isQ ? blk : blk - BB * NQ / PRE_ROWS) * PRE_ROWS;

    const float* inv  = (isQ ? q_inv : k_inv) + (size_t)rowbase * DINV;
    const float* W    = isQ ? Wq : Wk;
    const float* bias = isQ ? bq : bk;
    const float* W1s  = isQ ? W1 : (W1 + DMSG * DFF);
    __half* A         = (isQ ? g_Aqh : g_Akh) + (size_t)rowbase * DFF;

    __shared__ float s_inv[16 * 260];
    __shared__ float s_part[4 * 16 * 64];
    __shared__ float s_msg[16 * 68];

    int tid = threadIdx.x;

    for (int idx = tid; idx < 1024; idx += 256) {
        int row = idx >> 6, seg = idx & 63;
        *(float4*)&s_inv[row * 260 + seg * 4] = *(const float4*)(inv + row * 256 + seg * 4);
    }
    __syncthreads();

    {
        int m = tid & 63, g = tid >> 6;
        float acc[16];
        #pragma unroll
        for (int row = 0; row < 16; row++) acc[row] = 0.f;
        for (int i = g * 64; i < g * 64 + 64; i += 4) {
            float w0 = W[(i + 0) * DMSG + m];
            float w1 = W[(i + 1) * DMSG + m];
            float w2 = W[(i + 2) * DMSG + m];
            float w3 = W[(i + 3) * DMSG + m];
            #pragma unroll
            for (int row = 0; row < 16; row++) {
                float4 v = *(const float4*)&s_inv[row * 260 + i];
                acc[row] = fmaf(v.w, w3, fmaf(v.z, w2, fmaf(v.y, w1, fmaf(v.x, w0, acc[row]))));
            }
        }
        #pragma unroll
        for (int row = 0; row < 16; row++) s_part[(g * 16 + row) * 64 + m] = acc[row];
    }
    __syncthreads();
    for (int v = tid; v < 1024; v += 256) {
        int row = v >> 6, mm = v & 63;
        s_msg[row * 68 + mm] = s_part[row * 64 + mm] + s_part[(16 + row) * 64 + mm]
                             + s_part[(32 + row) * 64 + mm] + s_part[(48 + row) * 64 + mm]
                             + bias[mm];
    }
    __syncthreads();

    {
        int ff = tid;
        float binit = isQ ? b1[ff] : 0.f;
        float acc[16];
        #pragma unroll
        for (int row = 0; row < 16; row++) acc[row] = binit;
        for (int mm = 0; mm < 64; mm += 4) {
            float w0 = W1s[(mm + 0) * DFF + ff];
            float w1 = W1s[(mm + 1) * DFF + ff];
            float w2 = W1s[(mm + 2) * DFF + ff];
            float w3 = W1s[(mm + 3) * DFF + ff];
            #pragma unroll
            for (int row = 0; row < 16; row++) {
                float4 mv = *(const float4*)&s_msg[row * 68 + mm];
                acc[row] = fmaf(mv.w, w3, fmaf(mv.z, w2, fmaf(mv.y, w1, fmaf(mv.x, w0, acc[row]))));
            }
        }
        #pragma unroll
        for (int row = 0; row < 16; row++)
            A[row * DFF + ff] = __float2half(acc[row]);
    }
}

// ---------------- W1 chunk prefetch via cp.async ----------------
__device__ __forceinline__ void prefetch_w1(int c, uint32_t w1dst, int tid) {
    const char* src1 = (const char*)(g_W1T + c * 64 * LDA);
    #pragma unroll
    for (int i = tid; i < 1088; i += 256)
        CP_ASYNC16(w1dst + i * 16, src1 + i * 16);
}

// ---------------- main pairwise kernel (2 CTAs/SM) ----------------
__global__ void __launch_bounds__(256, 2) pair_kernel(
    const float* __restrict__ q_equi, const float* __restrict__ k_equi,
    const float* __restrict__ b2, float* __restrict__ out)
{
    extern __shared__ char smem[];
    const uint32_t sb = smem_u32(smem);
    int tid = threadIdx.x;
    int w = tid >> 5, lane = tid & 31;

    int b  = blockIdx.z;
    int q0 = blockIdx.y * TQ;
    int k0 = blockIdx.x * TK;

    const __half* sAqh = (const __half*)(smem + OFF_AQH);
    const __half* sAkh = (const __half*)(smem + OFF_AKH);
    const float*  sb2  = (const float*)(smem + OFF_B2);

    // ---- phase 0: async-stage equi (f32), Aq/Ak (f16), b2; prefetch W1 chunk0 ----
    {
        const char* qsrc = (const char*)(q_equi + (size_t)(b * NQ + q0) * 192);
        const char* ksrc = (const char*)(k_equi + (size_t)(b * NK + k0) * 192);
        #pragma unroll
        for (int i = tid; i < 768; i += 256)
            CP_ASYNC16(sb + OFF_QE + i * 16, qsrc + i * 16);
        for (int i = tid; i < 384; i += 256) {
            int row = i / 48, seg = i - row * 48;
            CP_ASYNC16(sb + OFF_KE + row * (LDKE * 4) + seg * 16,
                       ksrc + (row * 192 + seg * 4) * 4);
        }
        const char* aqsrc = (const char*)(g_Aqh + (size_t)(b * NQ + q0) * DFF);
        const char* aksrc = (const char*)(g_Akh + (size_t)(b * NK + k0) * DFF);
        #pragma unroll
        for (int i = tid; i < 512; i += 256) {
            int row = i >> 5, seg = i & 31;
            CP_ASYNC16(sb + OFF_AQH + row * (LDAQH * 2) + seg * 16, aqsrc + i * 16);
        }
        if (tid < 256) {
            int row = tid >> 5, seg = tid & 31;
            CP_ASYNC16(sb + OFF_AKH + row * (LDAQH * 2) + seg * 16, aksrc + tid * 16);
        }
        if (tid < 16) CP_ASYNC16(sb + OFF_B2 + tid * 16, (const char*)b2 + tid * 16);
        CP_COMMIT();                                       // G0: inputs
        prefetch_w1(0, sb + OFF_W1C0, tid);
        CP_COMMIT();                                       // G1: W1 chunk 0
        CP_WAIT(1);
        __syncthreads();
    }

    // ---- lane geometry ----
    const int r = lane >> 2, cp = (lane & 3) * 2;
    const int qi0 = 2 * w;

    // ---- P2: dot & dist -> GEMM1 A-fragments in registers ----
    uint32_t af[8][4];
    {
        const float* q0p = (const float*)(smem + OFF_QE) + qi0 * 192;
        const float* q1p = q0p + 192;
        const float* kp  = (const float*)(smem + OFF_KE) + r * LDKE;
        #pragma unroll
        for (int ww = 0; ww < 4; ww++) {
            #pragma unroll
            for (int hh = 0; hh < 2; hh++) {
                int e0 = ww * 16 + hh * 8 + cp;
                uint64_t k0v = pk2(*(const float2*)(kp + e0));
                uint64_t k1v = pk2(*(const float2*)(kp + e0 + 64));
                uint64_t k2v = pk2(*(const float2*)(kp + e0 + 128));
                uint64_t k0n = k0v ^ NEGMASK2;
                uint64_t k1n = k1v ^ NEGMASK2;
                uint64_t k2n = k2v ^ NEGMASK2;
                {
                    uint64_t a0 = pk2(*(const float2*)(q0p + e0));
                    uint64_t a1 = pk2(*(const float2*)(q0p + e0 + 64));
                    uint64_t a2 = pk2(*(const float2*)(q0p + e0 + 128));
                    uint64_t d  = fma2_(a2, k2v, fma2_(a1, k1v, mul2_(a0, k0v)));
                    uint64_t f0 = add2_(a0, k0n);
                    uint64_t f1 = add2_(a1, k1n);
                    uint64_t f2 = add2_(a2, k2n);
                    uint64_t s  = fma2_(f2, f2, fma2_(f1, f1, mul2_(f0, f0)));
                    float2 df = upk2(d), sf = upk2(s);
                    __half2 hd = __floats2half2_rn(df.x, df.y);
                    __half2 hs = __floats2half2_rn(sqrt_ap(sf.x), sqrt_ap(sf.y));
                    af[ww][hh * 2 + 0]     = *(uint32_t*)&hd;
                    af[ww + 4][hh * 2 + 0] = *(uint32_t*)&hs;
                }
                {
                    uint64_t a0 = pk2(*(const float2*)(q1p + e0));
                    uint64_t a1 = pk2(*(const float2*)(q1p + e0 + 64));
                    uint64_t a2 = pk2(*(const float2*)(q1p + e0 + 128));
                    uint64_t d  = fma2_(a2, k2v, fma2_(a1, k1v, mul2_(a0, k0v)));
                    uint64_t f0 = add2_(a0, k0n);
                    uint64_t f1 = add2_(a1, k1n);
                    uint64_t f2 = add2_(a2, k2n);
                    uint64_t s  = fma2_(f2, f2, fma2_(f1, f1, mul2_(f0, f0)));
                    float2 df = upk2(d), sf = upk2(s);
                    __half2 hd = __floats2half2_rn(df.x, df.y);
                    __half2 hs = __floats2half2_rn(sqrt_ap(sf.x), sqrt_ap(sf.y));
                    af[ww][hh * 2 + 1]     = *(uint32_t*)&hd;
                    af[ww + 4][hh * 2 + 1] = *(uint32_t*)&hs;
                }
            }
        }
    }

    // B-side ldmatrix bases (W1 buffers only)
    const int bRow = (lane & 7) + ((lane >> 4) << 3);
    const uint32_t bOff1 = (bRow * LDA + ((lane >> 3) & 1) * 8) * 2;
    const uint32_t b1Base[2] = { sb + OFF_W1C0 + bOff1, sb + OFF_W1C1 + bOff1 };
    const uint32_t w1Dst[2]  = { sb + OFF_W1C0, sb + OFF_W1C1 };

    // acc2 init = b2 (broadcast; same for lo/hi rows)
    float acc2[8][4];
    #pragma unroll
    for (int j = 0; j < 8; j++) {
        int n = j * 8 + cp;
        float2 bv = *(const float2*)(sb2 + n);
        acc2[j][0] = bv.x; acc2[j][1] = bv.y;
        acc2[j][2] = bv.x; acc2[j][3] = bv.y;
    }

    const uint4* w2f = (const uint4*)g_W2F + lane;   // + ((c*4+kk)*4+jp)*32

    // ================= chunk loop over N (4 x 64) =================
    for (int c = 0; c < 4; c++) {
        CP_WAIT(0);
        __syncthreads();

        if (c < 3) {
            prefetch_w1(c + 1, w1Dst[(c + 1) & 1], tid);
            CP_COMMIT();
        }

        const uint32_t bA1 = b1Base[c & 1];
        const uint4* w2c = w2f + c * 512;

        // ---- init acc1 with Aq + Ak (MMA C-operand) ----
        float acc1[8][4];
        {
            const __half* aqlo = sAqh + qi0 * LDAQH + c * 64;
            const __half* aqhi = aqlo + LDAQH;
            const __half* akr  = sAkh + r * LDAQH + c * 64;
            #pragma unroll
            for (int j = 0; j < 8; j++) {
                int n = j * 8 + cp;
                float2 aql = __half22float2(*(const __half2*)(aqlo + n));
                float2 aqh = __half22float2(*(const __half2*)(aqhi + n));
                float2 akl = __half22float2(*(const __half2*)(akr + n));
                acc1[j][0] = aql.x + akl.x;
                acc1[j][1] = aql.y + akl.y;
                acc1[j][2] = aqh.x + akl.x;
                acc1[j][3] = aqh.y + akl.y;
            }
        }

        // ---- GEMM1 chunk: acc1 += A[16,128] @ W1c^T (LDSM) ----
        #pragma unroll
        for (int kk = 0; kk < 8; kk++) {
            #pragma unroll
            for (int jp = 0; jp < 4; jp++) {
                uint32_t b0, b1r, b2r, b3;
                ldsm4(b0, b1r, b2r, b3, bA1 + jp * 16 * LDA * 2 + kk * 32);
                mma16816(acc1[2 * jp],     af[kk][0], af[kk][1], af[kk][2], af[kk][3], b0,  b1r);
                mma16816(acc1[2 * jp + 1], af[kk][0], af[kk][1], af[kk][2], af[kk][3], b2r, b3);
            }
        }

        // ---- prefetch W2 frags for kk=0,1 over L2 (af now dead) ----
        uint4 f2a[8];
        #pragma unroll
        for (int i = 0; i < 8; i++) f2a[i] = __ldg(w2c + i * 32);

        // ---- epilogue1: cvt + SiLU -> register h fragments ----
        uint32_t hlo[8], hhi[8];
        #pragma unroll
        for (int j = 0; j < 8; j++) {
            __half2 x0 = __floats2half2_rn(acc1[j][0], acc1[j][1]);
            __half2 x1 = __floats2half2_rn(acc1[j][2], acc1[j][3]);
            hlo[j] = silu_h2(*(uint32_t*)&x0);
            hhi[j] = silu_h2(*(uint32_t*)&x1);
        }

        // ---- prefetch W2 frags for kk=2,3 (acc1 now dead) ----
        uint4 f2b[8];
        #pragma unroll
        for (int i = 0; i < 8; i++) f2b[i] = __ldg(w2c + (8 + i) * 32);

        // ---- GEMM2 partial: acc2 += h[16,64] @ W2c^T (B from L2 fragments) ----
        #pragma unroll
        for (int kk = 0; kk < 2; kk++) {
            uint32_t a0 = hlo[2 * kk], a1 = hhi[2 * kk];
            uint32_t a2 = hlo[2 * kk + 1], a3 = hhi[2 * kk + 1];
            #pragma unroll
            for (int jp = 0; jp < 4; jp++) {
                uint4 f = f2a[kk * 4 + jp];
                mma16816(acc2[2 * jp],     a0, a1, a2, a3, f.x, f.y);
                mma16816(acc2[2 * jp + 1], a0, a1, a2, a3, f.z, f.w);
            }
        }
        #pragma unroll
        for (int kk = 2; kk < 4; kk++) {
            uint32_t a0 = hlo[2 * kk], a1 = hhi[2 * kk];
            uint32_t a2 = hlo[2 * kk + 1], a3 = hhi[2 * kk + 1];
            #pragma unroll
            for (int jp = 0; jp < 4; jp++) {
                uint4 f = f2b[(kk - 2) * 4 + jp];
                mma16816(acc2[2 * jp],     a0, a1, a2, a3, f.x, f.y);
                mma16816(acc2[2 * jp + 1], a0, a1, a2, a3, f.z, f.w);
            }
        }
    }

    // ---- epilogue2: store (b2 already folded into acc2 init) ----
    {
        float* olo = out + ((size_t)(b * NQ + q0 + qi0) * NK + (k0 + r)) * DOUT;
        float* ohi = olo + (size_t)NK * DOUT;
        #pragma unroll
        for (int j = 0; j < 8; j++) {
            int n = j * 8 + cp;
            float2 v0, v1;
            v0.x = acc2[j][0]; v0.y = acc2[j][1];
            v1.x = acc2[j][2]; v1.y = acc2[j][3];
            *(float2*)(olo + n) = v0;
            *(float2*)(ohi + n) = v1;
        }
    }
}

// ---------------------------------------------------------------------------
extern "C" void kernel_launch(void* const* d_in, const int* in_sizes, int n_in,
                              void* d_out, int out_size)
{
    const float* q_equi = (const float*)d_in[0];
    const float* q_inv  = (const float*)d_in[1];
    const float* k_equi = (const float*)d_in[2];
    const float* k_inv  = (const float*)d_in[3];
    const float* Wq     = (const float*)d_in[4];
    const float* bq     = (const float*)d_in[5];
    const float* Wk     = (const float*)d_in[6];
    const float* bk     = (const float*)d_in[7];
    const float* W1     = (const float*)d_in[8];
    const float* b1     = (const float*)d_in[9];
    const float* W2     = (const float*)d_in[10];
    const float* b2     = (const float*)d_in[11];
    float* out = (float*)d_out;

    cudaFuncSetAttribute(pair_kernel, cudaFuncAttributeMaxDynamicSharedMemorySize, SMEM_BYTES);

    prelude_kernel<<<NPRE2 + NPREP, 256>>>(q_inv, k_inv, Wq, bq, Wk, bk, W1, b1, W2);

    dim3 grid(NK / TK, NQ / TQ, BB);
    pair_kernel<<<grid, 256, SMEM_BYTES>>>(q_equi, k_equi, b2, out);
}